// round 3
// baseline (speedup 1.0000x reference)
#include <cuda_runtime.h>
#include <cuda_bf16.h>

#define BB 2
#define NN 16384
#define PP 4096
#define CC 64
#define SS 32
#define CH (3 + CC)   // 67
#define GC 10
#define NCELL (GC*GC*GC)
#define HB 320        // per-warp hit buffer capacity

// ---- scratch (__device__ globals; no cudaMalloc allowed) ----
// g_cnt is zero at module load; scatter's atomicSub countdown restores it to
// zero every launch, so the graph replays deterministically with no zeroing pass.
__device__ float4 g_xyz4[BB * NN];           // packed xyz, .w = cell id
__device__ float  g_ftrt[BB * NN * CC];      // features transposed to (B,N,C)
__device__ float4 g_pts [BB * NN];           // cell-sorted points, .w = idx
__device__ int    g_cnt [BB * NCELL];        // counts (self-restoring)
__device__ int    g_start[BB * (NCELL + 1)]; // exclusive scan

__device__ __forceinline__ int cell_of(float x, float y, float z) {
    int cx = min((int)(x * 10.0f), GC - 1);
    int cy = min((int)(y * 10.0f), GC - 1);
    int cz = min((int)(z * 10.0f), GC - 1);
    return (cz * GC + cy) * GC + cx;
}

// ---------------------------------------------------------------------------
// Pack xyz -> float4 (+cell in .w) and histogram cells. 4 points/thread via
// three coalesced float4 loads (48B per thread, 16B-aligned).
// ---------------------------------------------------------------------------
__global__ void pack_count_kernel(const float* __restrict__ xyz) {
    int t  = blockIdx.x * blockDim.x + threadIdx.x;
    int i0 = t * 4;
    if (i0 >= BB * NN) return;
    const float4* src = (const float4*)(xyz + (size_t)i0 * 3);
    float4 a = src[0], b4 = src[1], c4 = src[2];
    float px[4] = {a.x, a.w,  b4.z, c4.y};
    float py[4] = {a.y, b4.x, b4.w, c4.z};
    float pz[4] = {a.z, b4.y, c4.x, c4.w};
    int b = i0 / NN;                       // NN % 4 == 0 -> same batch
#pragma unroll
    for (int k = 0; k < 4; k++) {
        int cell = cell_of(px[k], py[k], pz[k]);
        g_xyz4[i0 + k] = make_float4(px[k], py[k], pz[k], __int_as_float(cell));
        atomicAdd(&g_cnt[b * NCELL + cell], 1);
    }
}

// ---------------------------------------------------------------------------
// Exclusive scan of 1000 counts per batch: shuffle warp-scan, 2 barriers/batch.
// Leaves g_cnt intact (scatter needs it for the countdown).
// ---------------------------------------------------------------------------
__global__ void scan_kernel() {
    __shared__ int wsum[32];
    int t = threadIdx.x, lane = t & 31, wid = t >> 5;
    for (int b = 0; b < BB; b++) {
        int v = (t < NCELL) ? g_cnt[b * NCELL + t] : 0;
        int s = v;
#pragma unroll
        for (int o = 1; o < 32; o <<= 1) {
            int u = __shfl_up_sync(0xffffffffu, s, o);
            if (lane >= o) s += u;
        }
        if (lane == 31) wsum[wid] = s;
        __syncthreads();
        if (wid == 0) {
            int ws = wsum[lane];
#pragma unroll
            for (int o = 1; o < 32; o <<= 1) {
                int u = __shfl_up_sync(0xffffffffu, ws, o);
                if (lane >= o) ws += u;
            }
            wsum[lane] = ws;
        }
        __syncthreads();
        int incl = s + (wid ? wsum[wid - 1] : 0);
        if (t < NCELL) g_start[b * (NCELL + 1) + t + 1] = incl;
        if (t == 0)    g_start[b * (NCELL + 1)] = 0;
        __syncthreads();
    }
}

// ---------------------------------------------------------------------------
// Scatter into cell-sorted order. Countdown atomics restore g_cnt to zero.
// 2 points/thread for MLP; reads the packed float4 (L2-hot).
// ---------------------------------------------------------------------------
__global__ void scatter_kernel() {
    int t  = blockIdx.x * blockDim.x + threadIdx.x;
    int i0 = t * 2;
    if (i0 >= BB * NN) return;
    int b = i0 / NN;
#pragma unroll
    for (int k = 0; k < 2; k++) {
        float4 p = g_xyz4[i0 + k];
        int c   = __float_as_int(p.w);
        int off = atomicSub(&g_cnt[b * NCELL + c], 1) - 1;
        int pos = g_start[b * (NCELL + 1) + c] + off;
        g_pts[b * NN + pos] =
            make_float4(p.x, p.y, p.z, __int_as_float(i0 + k - b * NN));
    }
}

// ---------------------------------------------------------------------------
// Transpose features (B,C,N) -> (B,N,C)
// ---------------------------------------------------------------------------
__global__ void transpose_feat_kernel(const float* __restrict__ f) {
    __shared__ float tile[32][33];
    int b  = blockIdx.z;
    int n0 = blockIdx.x * 32;
    int c0 = blockIdx.y * 32;
    int tx = threadIdx.x, ty = threadIdx.y;   // (32,8)
#pragma unroll
    for (int j = 0; j < 32; j += 8)
        tile[ty + j][tx] = f[((size_t)b * CC + (c0 + ty + j)) * NN + n0 + tx];
    __syncthreads();
#pragma unroll
    for (int j = 0; j < 32; j += 8)
        g_ftrt[((size_t)b * NN + (n0 + ty + j)) * CC + c0 + tx] = tile[tx][ty + j];
}

// ---------------------------------------------------------------------------
// Fused ball-query + grouping: one warp per query.
//  Phase 1: grid query -> hits in u.buf, rank by original index (PointNet++
//           first-nsample-in-index-order, pad with first hit / 0).
//  Phase 2: per-lane idx in sel[], feature gather staged through u.stage
//           (2 points per LDG.128), coalesced per-channel stores.
// Distance math + 0.01f threshold frozen (bit-exact since R1).
// ---------------------------------------------------------------------------
struct WarpScratch {
    int sel[32];
    union {
        int   buf[HB];
        float stage[32 * 65];
    } u;
};

__global__ void __launch_bounds__(128) query_group_kernel(
        const float* __restrict__ new_xyz, float* __restrict__ out) {
    __shared__ WarpScratch ws[4];
    int w    = (blockIdx.x * blockDim.x + threadIdx.x) >> 5;
    int lane = threadIdx.x & 31;
    if (w >= BB * PP) return;
    int b = w / PP;
    int p = w % PP;
    WarpScratch& S = ws[(threadIdx.x >> 5) & 3];

    float qx = new_xyz[3 * w + 0];
    float qy = new_xyz[3 * w + 1];
    float qz = new_xyz[3 * w + 2];

    // ---- phase 1: grid ball query ----
    int cx = min((int)(qx * 10.0f), GC - 1);
    int cy = min((int)(qy * 10.0f), GC - 1);
    int cz = min((int)(qz * 10.0f), GC - 1);
    int x0 = max(cx - 1, 0), x1 = min(cx + 1, GC - 1);

    const int*    st  = g_start + b * (NCELL + 1);
    const float4* pts = g_pts + (size_t)b * NN;

    int K = 0;
    for (int dz = -1; dz <= 1; dz++) {
        int z = cz + dz;
        if (z < 0 || z >= GC) continue;
        for (int dy = -1; dy <= 1; dy++) {
            int y = cy + dy;
            if (y < 0 || y >= GC) continue;
            int row = (z * GC + y) * GC;
            int rs = st[row + x0];
            int re = st[row + x1 + 1];
            for (int base = rs; base < re; base += 32) {
                int j = base + lane;
                bool hit = false; int id = 0;
                if (j < re) {
                    float4 pt = pts[j];
                    float dx = qx - pt.x, dy2 = qy - pt.y, dz2 = qz - pt.z;
                    float d2 = __fmaf_rn(dz2, dz2,
                               __fmaf_rn(dy2, dy2, __fmul_rn(dx, dx)));
                    hit = d2 < 0.01f;
                    id  = __float_as_int(pt.w);
                }
                unsigned m = __ballot_sync(0xffffffffu, hit);
                if (hit) {
                    int pos = K + __popc(m & ((1u << lane) - 1u));
                    if (pos < HB) S.u.buf[pos] = id;
                }
                K += __popc(m);
            }
        }
    }
    if (K > HB) K = HB;
    __syncwarp();

    // rank hits by original index
    int cnt  = min(K, SS);
    int padv = 0x7fffffff;
    int G = (K + 31) >> 5;
    for (int g = 0; g < G; g++) {
        int t = g * 32 + lane;
        bool val = t < K;
        int v = val ? S.u.buf[t] : 0x7fffffff;
        int r = 0;
        for (int u = 0; u < K; u++)          // broadcast LDS, conflict-free
            r += (S.u.buf[u] < v);
        if (val && r < SS) S.sel[r] = v;
        padv = min(padv, v);
    }
#pragma unroll
    for (int o = 16; o; o >>= 1)
        padv = min(padv, __shfl_xor_sync(0xffffffffu, padv, o));
    if (K == 0) padv = 0;
    __syncwarp();                            // sel writes + buf reads done

    int i = (lane < cnt) ? S.sel[lane] : padv;
    S.sel[lane] = i;                         // final per-slot index
    __syncwarp();

    // ---- phase 2: grouping ----
    float4 pt = g_xyz4[(size_t)b * NN + i];

    const size_t chStride = (size_t)PP * SS;
    size_t obase = (((size_t)b * CH) * PP + p) * SS + lane;

    out[obase + 0 * chStride] = pt.x - qx;
    out[obase + 1 * chStride] = pt.y - qy;
    out[obase + 2 * chStride] = pt.z - qz;

    // gather 32 points x 64ch, 2 points per LDG.128, stage in smem
    int half = lane >> 4;
    int c    = lane & 15;
#pragma unroll
    for (int j = 0; j < 16; j++) {
        int ptid = 2 * j + half;
        int ii = S.sel[ptid];
        const float4* src =
            (const float4*)(g_ftrt + ((size_t)b * NN + ii) * CC) + c;
        float4 v = *src;
        float* d = &S.u.stage[ptid * 65 + c * 4];
        d[0] = v.x; d[1] = v.y; d[2] = v.z; d[3] = v.w;
    }
    __syncwarp();

    size_t fo = obase + 3 * chStride;
#pragma unroll
    for (int ch = 0; ch < CC; ch++)
        out[fo + (size_t)ch * chStride] = S.u.stage[lane * 65 + ch];
}

// ---------------------------------------------------------------------------
extern "C" void kernel_launch(void* const* d_in, const int* in_sizes, int n_in,
                              void* d_out, int out_size) {
    const float* xyz     = (const float*)d_in[0];   // (2,16384,3)
    const float* new_xyz = (const float*)d_in[1];   // (2,4096,3)
    const float* feat    = (const float*)d_in[2];   // (2,64,16384)
    float* out = (float*)d_out;                     // (2,67,4096,32)

    pack_count_kernel<<<(BB * NN / 4 + 255) / 256, 256>>>(xyz);
    scan_kernel<<<1, 1024>>>();
    scatter_kernel<<<(BB * NN / 2 + 255) / 256, 256>>>();

    dim3 tb(32, 8), tg(NN / 32, CC / 32, BB);
    transpose_feat_kernel<<<tg, tb>>>(feat);

    query_group_kernel<<<(BB * PP) / 4, 128>>>(new_xyz, out);
}

// round 4
// speedup vs baseline: 1.1265x; 1.1265x over previous
#include <cuda_runtime.h>
#include <cuda_bf16.h>

#define BB 2
#define NN 16384
#define PP 4096
#define CC 64
#define SS 32
#define CH (3 + CC)   // 67
#define GC 10
#define NCELL (GC*GC*GC)
#define HB 320        // per-warp hit buffer capacity

// ---- scratch (__device__ globals; no cudaMalloc allowed) ----
// g_cnt is zero at module load; scatter's atomicSub countdown restores it to
// zero every launch -> graph replays deterministically with no zeroing pass.
__device__ float4 g_xyz4[BB * NN];           // packed xyz, .w = cell id
__device__ float  g_ftrt[BB * NN * CC];      // features transposed to (B,N,C)
__device__ float4 g_pts [BB * NN];           // cell-sorted points, .w = idx
__device__ int    g_cnt [BB * NCELL];        // counts (self-restoring)
__device__ int    g_start[BB * (NCELL + 1)]; // exclusive scan
__device__ int    g_idx [BB * PP * SS];      // ball query result

__device__ __forceinline__ int cell_of(float x, float y, float z) {
    int cx = min((int)(x * 10.0f), GC - 1);
    int cy = min((int)(y * 10.0f), GC - 1);
    int cz = min((int)(z * 10.0f), GC - 1);
    return (cz * GC + cy) * GC + cx;
}

// ---------------------------------------------------------------------------
// Pack xyz -> float4 (+cell in .w) and histogram cells. 4 points/thread via
// three coalesced float4 loads.
// ---------------------------------------------------------------------------
__global__ void pack_count_kernel(const float* __restrict__ xyz) {
    int t  = blockIdx.x * blockDim.x + threadIdx.x;
    int i0 = t * 4;
    if (i0 >= BB * NN) return;
    const float4* src = (const float4*)(xyz + (size_t)i0 * 3);
    float4 a = src[0], b4 = src[1], c4 = src[2];
    float px[4] = {a.x, a.w,  b4.z, c4.y};
    float py[4] = {a.y, b4.x, b4.w, c4.z};
    float pz[4] = {a.z, b4.y, c4.x, c4.w};
    int b = i0 / NN;                       // NN % 4 == 0 -> same batch
#pragma unroll
    for (int k = 0; k < 4; k++) {
        int cell = cell_of(px[k], py[k], pz[k]);
        g_xyz4[i0 + k] = make_float4(px[k], py[k], pz[k], __int_as_float(cell));
        atomicAdd(&g_cnt[b * NCELL + cell], 1);
    }
}

// ---------------------------------------------------------------------------
// Exclusive scan of 1000 counts per batch; shuffle warp-scan, 2 barriers.
// Leaves g_cnt intact (scatter consumes it as a countdown).
// ---------------------------------------------------------------------------
__global__ void scan_kernel() {
    __shared__ int wsum[32];
    int t = threadIdx.x, lane = t & 31, wid = t >> 5;
    for (int b = 0; b < BB; b++) {
        int v = (t < NCELL) ? g_cnt[b * NCELL + t] : 0;
        int s = v;
#pragma unroll
        for (int o = 1; o < 32; o <<= 1) {
            int u = __shfl_up_sync(0xffffffffu, s, o);
            if (lane >= o) s += u;
        }
        if (lane == 31) wsum[wid] = s;
        __syncthreads();
        if (wid == 0) {
            int ws = wsum[lane];
#pragma unroll
            for (int o = 1; o < 32; o <<= 1) {
                int u = __shfl_up_sync(0xffffffffu, ws, o);
                if (lane >= o) ws += u;
            }
            wsum[lane] = ws;
        }
        __syncthreads();
        int incl = s + (wid ? wsum[wid - 1] : 0);
        if (t < NCELL) g_start[b * (NCELL + 1) + t + 1] = incl;
        if (t == 0)    g_start[b * (NCELL + 1)] = 0;
        __syncthreads();
    }
}

// ---------------------------------------------------------------------------
// Scatter into cell-sorted order; countdown atomics restore g_cnt to zero.
// 1 point/thread (max parallelism; kernel is latency-bound).
// ---------------------------------------------------------------------------
__global__ void scatter_kernel() {
    int i = blockIdx.x * blockDim.x + threadIdx.x;
    if (i >= BB * NN) return;
    int b = i / NN;
    float4 p = g_xyz4[i];
    int c   = __float_as_int(p.w);
    int off = atomicSub(&g_cnt[b * NCELL + c], 1) - 1;
    int pos = g_start[b * (NCELL + 1) + c] + off;
    g_pts[b * NN + pos] = make_float4(p.x, p.y, p.z, __int_as_float(i - b * NN));
}

// ---------------------------------------------------------------------------
// Transpose features (B,C,N) -> (B,N,C) without smem:
// each thread reads 4 channels of one point (4 coalesced 128B warp-loads)
// and writes one STG.128 to the transposed row. 16B stores to distinct lines
// merge in L2 (8.4MB resident), so DRAM sees full sectors.
// ---------------------------------------------------------------------------
__global__ void transpose_feat_kernel(const float* __restrict__ f) {
    int n  = blockIdx.x * blockDim.x + threadIdx.x;   // 0..NN-1
    int c0 = blockIdx.y * 4;
    int b  = blockIdx.z;
    const float* base = f + ((size_t)b * CC + c0) * NN + n;
    float4 v;
    v.x = base[0 * NN];
    v.y = base[1 * NN];
    v.z = base[2 * NN];
    v.w = base[3 * NN];
    *(float4*)(g_ftrt + ((size_t)b * NN + n) * CC + c0) = v;
}

// ---------------------------------------------------------------------------
// Grid ball query: one warp per query. Scan 9 contiguous cell ranges,
// collect all hits, rank by original index (PointNet++ first-nsample-
// in-index-order, pad with first hit / 0). Math + 0.01f frozen (bit-exact).
// ---------------------------------------------------------------------------
__global__ void ball_query_grid_kernel(const float* __restrict__ new_xyz) {
    __shared__ int hb[8][HB];
    int w    = (blockIdx.x * blockDim.x + threadIdx.x) >> 5;
    int lane = threadIdx.x & 31;
    if (w >= BB * PP) return;
    int b = w / PP;
    int* buf = hb[(threadIdx.x >> 5) & 7];

    float qx = new_xyz[3 * w + 0];
    float qy = new_xyz[3 * w + 1];
    float qz = new_xyz[3 * w + 2];
    int cx = min((int)(qx * 10.0f), GC - 1);
    int cy = min((int)(qy * 10.0f), GC - 1);
    int cz = min((int)(qz * 10.0f), GC - 1);
    int x0 = max(cx - 1, 0), x1 = min(cx + 1, GC - 1);

    const int*    st  = g_start + b * (NCELL + 1);
    const float4* pts = g_pts + (size_t)b * NN;

    int K = 0;
    for (int dz = -1; dz <= 1; dz++) {
        int z = cz + dz;
        if (z < 0 || z >= GC) continue;
        for (int dy = -1; dy <= 1; dy++) {
            int y = cy + dy;
            if (y < 0 || y >= GC) continue;
            int row = (z * GC + y) * GC;
            int rs = st[row + x0];
            int re = st[row + x1 + 1];
            for (int base = rs; base < re; base += 32) {
                int j = base + lane;
                bool hit = false; int id = 0;
                if (j < re) {
                    float4 pt = pts[j];
                    float dx = qx - pt.x, dy2 = qy - pt.y, dz2 = qz - pt.z;
                    float d2 = __fmaf_rn(dz2, dz2,
                               __fmaf_rn(dy2, dy2, __fmul_rn(dx, dx)));
                    hit = d2 < 0.01f;
                    id  = __float_as_int(pt.w);
                }
                unsigned m = __ballot_sync(0xffffffffu, hit);
                if (hit) {
                    int pos = K + __popc(m & ((1u << lane) - 1u));
                    if (pos < HB) buf[pos] = id;
                }
                K += __popc(m);
            }
        }
    }
    if (K > HB) K = HB;
    __syncwarp();

    int* out = g_idx + (size_t)w * SS;
    int cnt  = min(K, SS);
    int padv = 0x7fffffff;
    int G = (K + 31) >> 5;
    for (int g = 0; g < G; g++) {
        int t = g * 32 + lane;
        bool val = t < K;
        int v = val ? buf[t] : 0x7fffffff;
        int r = 0;
        for (int u = 0; u < K; u++)          // broadcast LDS, conflict-free
            r += (buf[u] < v);
        if (val && r < SS) out[r] = v;
        padv = min(padv, v);
    }
#pragma unroll
    for (int o = 16; o; o >>= 1)
        padv = min(padv, __shfl_xor_sync(0xffffffffu, padv, o));
    if (K == 0) padv = 0;
    if (lane >= cnt) out[lane] = padv;       // pad with first (= min index)
}

// ---------------------------------------------------------------------------
// Grouping: one warp per query; feature gather staged through smem
// (2 points per LDG.128), per-channel stores perfectly coalesced.
// ---------------------------------------------------------------------------
__global__ void __launch_bounds__(128) group_kernel(
        const float* __restrict__ new_xyz, float* __restrict__ out) {
    __shared__ float stage[4][32][65];
    int w    = (blockIdx.x * blockDim.x + threadIdx.x) >> 5;
    int lane = threadIdx.x & 31;
    if (w >= BB * PP) return;
    int b = w / PP;
    int p = w % PP;
    float (*st)[65] = stage[(threadIdx.x >> 5) & 3];

    int i = g_idx[(size_t)w * SS + lane];

    float qx = new_xyz[3 * w + 0];
    float qy = new_xyz[3 * w + 1];
    float qz = new_xyz[3 * w + 2];

    float4 pt = g_xyz4[(size_t)b * NN + i];

    const size_t chStride = (size_t)PP * SS;
    size_t obase = (((size_t)b * CH) * PP + p) * SS + lane;

    out[obase + 0 * chStride] = pt.x - qx;
    out[obase + 1 * chStride] = pt.y - qy;
    out[obase + 2 * chStride] = pt.z - qz;

    int half = lane >> 4;          // 0: point 2j, 1: point 2j+1
    int c    = lane & 15;          // 16B chunk within point row
#pragma unroll
    for (int j = 0; j < 16; j++) {
        int ptid = 2 * j + half;
        int ii = __shfl_sync(0xffffffffu, i, ptid);
        const float4* src =
            (const float4*)(g_ftrt + ((size_t)b * NN + ii) * CC) + c;
        float4 v = *src;
        float* d = &st[ptid][c * 4];
        d[0] = v.x; d[1] = v.y; d[2] = v.z; d[3] = v.w;
    }
    __syncwarp();

    size_t fo = obase + 3 * chStride;
#pragma unroll
    for (int ch = 0; ch < CC; ch++)
        out[fo + (size_t)ch * chStride] = st[lane][ch];
}

// ---------------------------------------------------------------------------
extern "C" void kernel_launch(void* const* d_in, const int* in_sizes, int n_in,
                              void* d_out, int out_size) {
    const float* xyz     = (const float*)d_in[0];   // (2,16384,3)
    const float* new_xyz = (const float*)d_in[1];   // (2,4096,3)
    const float* feat    = (const float*)d_in[2];   // (2,64,16384)
    float* out = (float*)d_out;                     // (2,67,4096,32)

    pack_count_kernel<<<(BB * NN / 4 + 255) / 256, 256>>>(xyz);
    scan_kernel<<<1, 1024>>>();
    scatter_kernel<<<(BB * NN + 255) / 256, 256>>>();

    dim3 tg(NN / 256, CC / 4, BB);
    transpose_feat_kernel<<<tg, 256>>>(feat);

    ball_query_grid_kernel<<<(BB * PP) / 8, 256>>>(new_xyz);
    group_kernel<<<(BB * PP) / 4, 128>>>(new_xyz, out);
}

// round 5
// speedup vs baseline: 1.2209x; 1.0838x over previous
#include <cuda_runtime.h>
#include <cuda_bf16.h>

#define BB 2
#define NN 16384
#define PP 4096
#define CC 64
#define SS 32
#define CH (3 + CC)   // 67
#define GC 10
#define NCELL (GC*GC*GC)
#define HB 320        // per-warp hit buffer capacity

// ---- scratch (__device__ globals; no cudaMalloc allowed) ----
// g_cnt is zero at module load; scatter's atomicSub countdown restores it to
// zero every launch -> graph replays deterministically with no zeroing pass.
__device__ float4 g_xyz4[BB * NN];           // packed xyz, .w = cell id
__device__ float  g_ftrt[BB * NN * CC];      // features transposed to (B,N,C)
__device__ float4 g_pts [BB * NN];           // cell-sorted points, .w = idx
__device__ int    g_cnt [BB * NCELL];        // counts (self-restoring)
__device__ int    g_start[BB * (NCELL + 1)]; // exclusive scan
__device__ int    g_idx [BB * PP * SS];      // ball query result

__device__ __forceinline__ int cell_of(float x, float y, float z) {
    int cx = min((int)(x * 10.0f), GC - 1);
    int cy = min((int)(y * 10.0f), GC - 1);
    int cz = min((int)(z * 10.0f), GC - 1);
    return (cz * GC + cy) * GC + cx;
}

// ---------------------------------------------------------------------------
// Pack xyz -> float4 (+cell in .w) and histogram cells. 4 points/thread via
// three coalesced float4 loads.
// ---------------------------------------------------------------------------
__global__ void pack_count_kernel(const float* __restrict__ xyz) {
    int t  = blockIdx.x * blockDim.x + threadIdx.x;
    int i0 = t * 4;
    if (i0 >= BB * NN) return;
    const float4* src = (const float4*)(xyz + (size_t)i0 * 3);
    float4 a = src[0], b4 = src[1], c4 = src[2];
    float px[4] = {a.x, a.w,  b4.z, c4.y};
    float py[4] = {a.y, b4.x, b4.w, c4.z};
    float pz[4] = {a.z, b4.y, c4.x, c4.w};
    int b = i0 / NN;                       // NN % 4 == 0 -> same batch
#pragma unroll
    for (int k = 0; k < 4; k++) {
        int cell = cell_of(px[k], py[k], pz[k]);
        g_xyz4[i0 + k] = make_float4(px[k], py[k], pz[k], __int_as_float(cell));
        atomicAdd(&g_cnt[b * NCELL + cell], 1);
    }
}

// ---------------------------------------------------------------------------
// Exclusive scan of 1000 counts; one block per batch. Shuffle warp-scan.
// Leaves g_cnt intact (scatter consumes it as a countdown).
// ---------------------------------------------------------------------------
__global__ void scan_kernel() {
    __shared__ int wsum[32];
    int b = blockIdx.x;
    int t = threadIdx.x, lane = t & 31, wid = t >> 5;
    int v = (t < NCELL) ? g_cnt[b * NCELL + t] : 0;
    int s = v;
#pragma unroll
    for (int o = 1; o < 32; o <<= 1) {
        int u = __shfl_up_sync(0xffffffffu, s, o);
        if (lane >= o) s += u;
    }
    if (lane == 31) wsum[wid] = s;
    __syncthreads();
    if (wid == 0) {
        int ws = wsum[lane];
#pragma unroll
        for (int o = 1; o < 32; o <<= 1) {
            int u = __shfl_up_sync(0xffffffffu, ws, o);
            if (lane >= o) ws += u;
        }
        wsum[lane] = ws;
    }
    __syncthreads();
    int incl = s + (wid ? wsum[wid - 1] : 0);
    if (t < NCELL) g_start[b * (NCELL + 1) + t + 1] = incl;
    if (t == 0)    g_start[b * (NCELL + 1)] = 0;
}

// ---------------------------------------------------------------------------
// Fused: transpose features (B,C,N)->(B,N,C)  +  scatter points into
// cell-sorted order. Independent work, disjoint outputs; the transpose
// rides in the scatter's latency shadow instead of the critical path.
//
// Transpose tile: 32ch x 32pts, LDG.128 along N -> smem (stride 33, both
// phases bank-conflict-free) -> STG.128 along C.
// ---------------------------------------------------------------------------
#define TBLK (2048)                 // (NN/32)*(CC/32)*BB transpose blocks
#define SBLK ((BB * NN) / 256)      // 128 scatter blocks

__global__ void __launch_bounds__(256) scatter_transpose_kernel(
        const float* __restrict__ f) {
    __shared__ float tile[32][33];
    int bx = blockIdx.x;
    if (bx < TBLK) {
        // ---- transpose part ----
        int nt = NN / 32;                       // 512 n-tiles
        int b  = bx / (nt * 2);                 // CC/32 = 2
        int r  = bx % (nt * 2);
        int c0 = (r / nt) * 32;
        int n0 = (r % nt) * 32;
        int t  = threadIdx.x;
        {   // load: thread (c = t>>3, n4 = t&7) reads float4 along N
            int c = t >> 3, n4 = t & 7;
            float4 v = *(const float4*)(f + ((size_t)b * CC + c0 + c) * NN
                                          + n0 + n4 * 4);
            tile[c][n4 * 4 + 0] = v.x;
            tile[c][n4 * 4 + 1] = v.y;
            tile[c][n4 * 4 + 2] = v.z;
            tile[c][n4 * 4 + 3] = v.w;
        }
        __syncthreads();
        {   // store: thread (n = t>>3, c4 = t&7) writes float4 along C
            int n = t >> 3, c4 = t & 7;
            float4 v;
            v.x = tile[c4 * 4 + 0][n];
            v.y = tile[c4 * 4 + 1][n];
            v.z = tile[c4 * 4 + 2][n];
            v.w = tile[c4 * 4 + 3][n];
            *(float4*)(g_ftrt + ((size_t)b * NN + n0 + n) * CC + c0 + c4 * 4) = v;
        }
    } else {
        // ---- scatter part ----
        int i = (bx - TBLK) * 256 + threadIdx.x;
        if (i >= BB * NN) return;
        int b = i / NN;
        float4 p = g_xyz4[i];
        int c   = __float_as_int(p.w);
        int off = atomicSub(&g_cnt[b * NCELL + c], 1) - 1;
        int pos = g_start[b * (NCELL + 1) + c] + off;
        g_pts[b * NN + pos] =
            make_float4(p.x, p.y, p.z, __int_as_float(i - b * NN));
    }
}

// ---------------------------------------------------------------------------
// Grid ball query: one warp per query. Scan 9 contiguous cell ranges,
// collect all hits, rank by original index (PointNet++ first-nsample-
// in-index-order, pad with first hit / 0). Math + 0.01f frozen (bit-exact).
// ---------------------------------------------------------------------------
__global__ void ball_query_grid_kernel(const float* __restrict__ new_xyz) {
    __shared__ int hb[8][HB];
    int w    = (blockIdx.x * blockDim.x + threadIdx.x) >> 5;
    int lane = threadIdx.x & 31;
    if (w >= BB * PP) return;
    int b = w / PP;
    int* buf = hb[(threadIdx.x >> 5) & 7];

    float qx = new_xyz[3 * w + 0];
    float qy = new_xyz[3 * w + 1];
    float qz = new_xyz[3 * w + 2];
    int cx = min((int)(qx * 10.0f), GC - 1);
    int cy = min((int)(qy * 10.0f), GC - 1);
    int cz = min((int)(qz * 10.0f), GC - 1);
    int x0 = max(cx - 1, 0), x1 = min(cx + 1, GC - 1);

    const int*    st  = g_start + b * (NCELL + 1);
    const float4* pts = g_pts + (size_t)b * NN;

    int K = 0;
    for (int dz = -1; dz <= 1; dz++) {
        int z = cz + dz;
        if (z < 0 || z >= GC) continue;
        for (int dy = -1; dy <= 1; dy++) {
            int y = cy + dy;
            if (y < 0 || y >= GC) continue;
            int row = (z * GC + y) * GC;
            int rs = st[row + x0];
            int re = st[row + x1 + 1];
            for (int base = rs; base < re; base += 32) {
                int j = base + lane;
                bool hit = false; int id = 0;
                if (j < re) {
                    float4 pt = pts[j];
                    float dx = qx - pt.x, dy2 = qy - pt.y, dz2 = qz - pt.z;
                    float d2 = __fmaf_rn(dz2, dz2,
                               __fmaf_rn(dy2, dy2, __fmul_rn(dx, dx)));
                    hit = d2 < 0.01f;
                    id  = __float_as_int(pt.w);
                }
                unsigned m = __ballot_sync(0xffffffffu, hit);
                if (hit) {
                    int pos = K + __popc(m & ((1u << lane) - 1u));
                    if (pos < HB) buf[pos] = id;
                }
                K += __popc(m);
            }
        }
    }
    if (K > HB) K = HB;
    __syncwarp();

    int* out = g_idx + (size_t)w * SS;
    int cnt  = min(K, SS);
    int padv = 0x7fffffff;
    int G = (K + 31) >> 5;
    for (int g = 0; g < G; g++) {
        int t = g * 32 + lane;
        bool val = t < K;
        int v = val ? buf[t] : 0x7fffffff;
        int r = 0;
        for (int u = 0; u < K; u++)          // broadcast LDS, conflict-free
            r += (buf[u] < v);
        if (val && r < SS) out[r] = v;
        padv = min(padv, v);
    }
#pragma unroll
    for (int o = 16; o; o >>= 1)
        padv = min(padv, __shfl_xor_sync(0xffffffffu, padv, o));
    if (K == 0) padv = 0;
    if (lane >= cnt) out[lane] = padv;       // pad with first (= min index)
}

// ---------------------------------------------------------------------------
// Grouping: one warp per query; feature gather staged through smem
// (2 points per LDG.128), per-channel stores perfectly coalesced.
// ---------------------------------------------------------------------------
__global__ void __launch_bounds__(128) group_kernel(
        const float* __restrict__ new_xyz, float* __restrict__ out) {
    __shared__ float stage[4][32][65];
    int w    = (blockIdx.x * blockDim.x + threadIdx.x) >> 5;
    int lane = threadIdx.x & 31;
    if (w >= BB * PP) return;
    int b = w / PP;
    int p = w % PP;
    float (*st)[65] = stage[(threadIdx.x >> 5) & 3];

    int i = g_idx[(size_t)w * SS + lane];

    float qx = new_xyz[3 * w + 0];
    float qy = new_xyz[3 * w + 1];
    float qz = new_xyz[3 * w + 2];

    float4 pt = g_xyz4[(size_t)b * NN + i];

    const size_t chStride = (size_t)PP * SS;
    size_t obase = (((size_t)b * CH) * PP + p) * SS + lane;

    out[obase + 0 * chStride] = pt.x - qx;
    out[obase + 1 * chStride] = pt.y - qy;
    out[obase + 2 * chStride] = pt.z - qz;

    int half = lane >> 4;          // 0: point 2j, 1: point 2j+1
    int c    = lane & 15;          // 16B chunk within point row
#pragma unroll
    for (int j = 0; j < 16; j++) {
        int ptid = 2 * j + half;
        int ii = __shfl_sync(0xffffffffu, i, ptid);
        const float4* src =
            (const float4*)(g_ftrt + ((size_t)b * NN + ii) * CC) + c;
        float4 v = *src;
        float* d = &st[ptid][c * 4];
        d[0] = v.x; d[1] = v.y; d[2] = v.z; d[3] = v.w;
    }
    __syncwarp();

    size_t fo = obase + 3 * chStride;
#pragma unroll
    for (int ch = 0; ch < CC; ch++)
        out[fo + (size_t)ch * chStride] = st[lane][ch];
}

// ---------------------------------------------------------------------------
extern "C" void kernel_launch(void* const* d_in, const int* in_sizes, int n_in,
                              void* d_out, int out_size) {
    const float* xyz     = (const float*)d_in[0];   // (2,16384,3)
    const float* new_xyz = (const float*)d_in[1];   // (2,4096,3)
    const float* feat    = (const float*)d_in[2];   // (2,64,16384)
    float* out = (float*)d_out;                     // (2,67,4096,32)

    pack_count_kernel<<<(BB * NN / 4 + 255) / 256, 256>>>(xyz);
    scan_kernel<<<BB, 1024>>>();
    scatter_transpose_kernel<<<TBLK + SBLK, 256>>>(feat);
    ball_query_grid_kernel<<<(BB * PP) / 8, 256>>>(new_xyz);
    group_kernel<<<(BB * PP) / 4, 128>>>(new_xyz, out);
}